// round 14
// baseline (speedup 1.0000x reference)
#include <cuda_runtime.h>
#include <cuda_bf16.h>
#include <cuda_fp16.h>
#include <cstdint>

#define Dd 64
#define Rr 8
#define MAXN 100000
#define MAXE 3200000
#define NCHUNK 9                  // 8 relations + root

// ---------------- device scratch (no allocation allowed) -------------------
__device__ __align__(256) unsigned g_hw16[(size_t)Rr * MAXN * 32]; // 102MB half2
__device__ __align__(256) float    g_h1[MAXN * Dd];
__device__ __align__(256) unsigned g_bhi[NCHUNK * 64 * 32];
__device__ __align__(256) unsigned g_blo[NCHUNK * 64 * 32];
__device__ __align__(256) int      g_base[MAXN * Rr + 1]; // seg = r*N+dst
__device__ __align__(256) int      g_cur[MAXN * Rr];
__device__ __align__(256) int      g_bsum[1024];
__device__ __align__(256) int      g_ssrc[MAXE];          // seg-sorted src ids

// ---------------- sort kernels (seg = r*N + dst) ----------------------------
__global__ void zeroi_kernel(int* __restrict__ p, int n) {
    int i = blockIdx.x * blockDim.x + threadIdx.x;
    int stride = gridDim.x * blockDim.x;
    for (; i < n; i += stride) p[i] = 0;
}
__global__ void hist_kernel(const int* __restrict__ ei,
                            const int* __restrict__ et, int n, int E_) {
    int stride = gridDim.x * blockDim.x;
    for (int e = blockIdx.x * blockDim.x + threadIdx.x; e < E_; e += stride)
        atomicAdd(&g_base[et[e] * n + ei[E_ + e]], 1);
}
__global__ void scan1_kernel(int S) {
    __shared__ int sh[256];
    int tid = threadIdx.x;
    int i0 = blockIdx.x * 1024 + tid * 4;
    int v[4], t = 0;
    #pragma unroll
    for (int j = 0; j < 4; ++j) {
        int idx = i0 + j;
        v[j] = (idx < S) ? g_base[idx] : 0;
        t += v[j];
    }
    sh[tid] = t;
    __syncthreads();
    for (int off = 1; off < 256; off <<= 1) {
        int x = (tid >= off) ? sh[tid - off] : 0;
        __syncthreads();
        sh[tid] += x;
        __syncthreads();
    }
    int run = sh[tid] - t;
    if (tid == 255) g_bsum[blockIdx.x] = sh[255];
    #pragma unroll
    for (int j = 0; j < 4; ++j) {
        int idx = i0 + j;
        if (idx < S) g_base[idx] = run;
        run += v[j];
    }
}
__global__ void scan2_kernel(int nb) {
    __shared__ int sh[256];
    int tid = threadIdx.x;
    int v[4], t = 0;
    #pragma unroll
    for (int j = 0; j < 4; ++j) {
        int idx = tid * 4 + j;
        v[j] = (idx < nb) ? g_bsum[idx] : 0;
        t += v[j];
    }
    sh[tid] = t;
    __syncthreads();
    for (int off = 1; off < 256; off <<= 1) {
        int x = (tid >= off) ? sh[tid - off] : 0;
        __syncthreads();
        sh[tid] += x;
        __syncthreads();
    }
    int run = sh[tid] - t;
    #pragma unroll
    for (int j = 0; j < 4; ++j) {
        int idx = tid * 4 + j;
        if (idx < nb) g_bsum[idx] = run;
        run += v[j];
    }
}
__global__ void scan3_kernel(int S, int E_) {
    int i = blockIdx.x * blockDim.x + threadIdx.x;
    if (i < S) {
        int b = g_base[i] + g_bsum[i >> 10];
        g_base[i] = b;
        g_cur[i]  = b;
    }
    if (i == 0) g_base[S] = E_;
}
__global__ void place_kernel(const int* __restrict__ ei,
                             const int* __restrict__ et, int n, int E_) {
    int stride = gridDim.x * blockDim.x;
    for (int e = blockIdx.x * blockDim.x + threadIdx.x; e < E_; e += stride) {
        int seg = et[e] * n + ei[E_ + e];
        int pos = atomicAdd(&g_cur[seg], 1);
        g_ssrc[pos] = ei[e];
    }
}

// ---------------- bf16 split helpers ---------------------------------------
__device__ __forceinline__ void split2(float a, float b, unsigned& hi, unsigned& lo) {
    __nv_bfloat16 ha = __float2bfloat16_rn(a), hb = __float2bfloat16_rn(b);
    float ra = a - __bfloat162float(ha), rb = b - __bfloat162float(hb);
    __nv_bfloat162 H = __nv_bfloat162(ha, hb);
    __nv_bfloat162 L = __nv_bfloat162(__float2bfloat16_rn(ra), __float2bfloat16_rn(rb));
    hi = *reinterpret_cast<unsigned*>(&H);
    lo = *reinterpret_cast<unsigned*>(&L);
}

// B-split + transpose: [c][outcol][k] rows for ldmatrix row.col.
__global__ void splitb_kernel(const float* __restrict__ W,
                              const float* __restrict__ root) {
    int j = blockIdx.x * blockDim.x + threadIdx.x;
    if (j >= NCHUNK * 64 * 32) return;
    int q = j & 31, col = (j >> 5) & 63, c = j >> 11;
    const float* B = (c < 8) ? (W + c * 4096) : root;
    float a = B[(2 * q) * 64 + col];
    float b = B[(2 * q + 1) * 64 + col];
    unsigned hi, lo;
    split2(a, b, hi, lo);
    g_bhi[j] = hi; g_blo[j] = lo;
}

// ---------------- mma.sync GEMM -----------------------------------------
// A loaded fp32 from h (mode 0: emb[x[row]]; mode 1: relu(h[row])), split
// to bf16 hi/lo in registers. chunks 0..7 -> fp16 hw planes; chunk 8 (root)
// -> fp32 out = C + bias.
#define BPITCH   144
#define SB_CHUNK (64 * BPITCH)
#define SB_HALF  (NCHUNK * SB_CHUNK)
#define SB_TOTAL (2 * SB_HALF)          // 165888 B
#define SM_BIAS  SB_TOTAL
#define SM_TOTAL (SM_BIAS + 256)

#define MMA(c0,c1,c2,c3, a, b0, b1)                                            \
    asm volatile("mma.sync.aligned.m16n8k16.row.col.f32.bf16.bf16.f32 "        \
                 "{%0,%1,%2,%3}, {%4,%5,%6,%7}, {%8,%9}, {%0,%1,%2,%3};"       \
                 : "+f"(c0), "+f"(c1), "+f"(c2), "+f"(c3)                      \
                 : "r"((a)[0]), "r"((a)[1]), "r"((a)[2]), "r"((a)[3]),         \
                   "r"(b0), "r"(b1))
#define LDSM_X2(b0, b1, addr)                                                  \
    asm volatile("ldmatrix.sync.aligned.m8n8.x2.shared.b16 {%0,%1}, [%2];"     \
                 : "=r"(b0), "=r"(b1) : "r"(addr))

__device__ __forceinline__ unsigned packh2(float a, float b) {
    __half2 h = __floats2half2_rn(a, b);
    return *reinterpret_cast<unsigned*>(&h);
}

__global__ __launch_bounds__(512, 1)
void gemm_mma(const float* __restrict__ h, const int* __restrict__ x,
              int mode, const float* __restrict__ bias,
              float* __restrict__ out, int nNodes) {
    extern __shared__ char sm[];
    int tid = threadIdx.x;

    for (int i = tid; i < NCHUNK * 64 * 32; i += 512) {
        int c = i >> 11, col = (i >> 5) & 63, q = i & 31;
        int off = c * SB_CHUNK + col * BPITCH + q * 4;
        *(unsigned*)(sm + off)           = g_bhi[i];
        *(unsigned*)(sm + SB_HALF + off) = g_blo[i];
    }
    if (tid < 64) ((float*)(sm + SM_BIAS))[tid] = bias[tid];
    __syncthreads();

    uint32_t smb;
    asm("{ .reg .u64 t; cvta.to.shared.u64 t, %1; cvt.u32.u64 %0, t; }"
        : "=r"(smb) : "l"(sm));
    const float* sbias = (const float*)(sm + SM_BIAS);

    int warp = tid >> 5, lane = tid & 31;
    int qt = lane & 3;
    uint32_t bbase = smb + (lane & 7) * BPITCH + ((lane >> 3) & 1) * 16;

    int ntiles = (nNodes + 255) >> 8;
    for (int tile = blockIdx.x; tile < ntiles; tile += gridDim.x) {
        int nbase = tile * 256 + warp * 16;
        int r0 = nbase + (lane >> 2);
        int r1 = r0 + 8;
        bool v0 = r0 < nNodes, v1 = r1 < nNodes;

        // A fragments: fp32 loads, optional relu, in-register bf16 split
        size_t row0 = 0, row1 = 0;
        if (v0) row0 = (mode == 0) ? (size_t)x[r0] : (size_t)r0;
        if (v1) row1 = (mode == 0) ? (size_t)x[r1] : (size_t)r1;
        const float2* p0 = (const float2*)h + row0 * 32;
        const float2* p1 = (const float2*)h + row1 * 32;

        unsigned ah[4][4], al[4][4];
        #pragma unroll
        for (int s = 0; s < 4; ++s) {
            int i0 = s * 8 + qt;
            float2 a0 = make_float2(0.f, 0.f), a1 = a0, a2 = a0, a3 = a0;
            if (v0) { a0 = p0[i0]; a2 = p0[i0 + 4]; }
            if (v1) { a1 = p1[i0]; a3 = p1[i0 + 4]; }
            if (mode == 1) {
                a0.x = fmaxf(a0.x, 0.f); a0.y = fmaxf(a0.y, 0.f);
                a1.x = fmaxf(a1.x, 0.f); a1.y = fmaxf(a1.y, 0.f);
                a2.x = fmaxf(a2.x, 0.f); a2.y = fmaxf(a2.y, 0.f);
                a3.x = fmaxf(a3.x, 0.f); a3.y = fmaxf(a3.y, 0.f);
            }
            split2(a0.x, a0.y, ah[s][0], al[s][0]);
            split2(a1.x, a1.y, ah[s][1], al[s][1]);
            split2(a2.x, a2.y, ah[s][2], al[s][2]);
            split2(a3.x, a3.y, ah[s][3], al[s][3]);
        }

        for (int c = 0; c < NCHUNK; ++c) {
            uint32_t cb = bbase + c * SB_CHUNK;
            unsigned* dst0 = g_hw16 + ((size_t)c * nNodes + r0) * 32;
            unsigned* dst1 = g_hw16 + ((size_t)c * nNodes + r1) * 32;
            #pragma unroll
            for (int j = 0; j < 8; ++j) {
                float c0 = 0.f, c1 = 0.f, c2 = 0.f, c3 = 0.f;
                uint32_t jb = cb + j * 8 * BPITCH;
                #pragma unroll
                for (int s = 0; s < 4; ++s) {
                    unsigned bh0, bh1, bl0, bl1;
                    LDSM_X2(bh0, bh1, jb + s * 32);
                    LDSM_X2(bl0, bl1, jb + s * 32 + SB_HALF);
                    MMA(c0, c1, c2, c3, ah[s], bh0, bh1);
                    MMA(c0, c1, c2, c3, ah[s], bl0, bl1);
                    MMA(c0, c1, c2, c3, al[s], bh0, bh1);
                }
                if (c < 8) {
                    int hcol = j * 4 + qt;     // half2 index within row
                    if (v0) dst0[hcol] = packh2(c0, c1);
                    if (v1) dst1[hcol] = packh2(c2, c3);
                } else {
                    int col = j * 8 + qt * 2;
                    float b0 = sbias[col], b1 = sbias[col + 1];
                    if (v0) *(float2*)(out + (size_t)r0 * Dd + col) =
                        make_float2(c0 + b0, c1 + b1);
                    if (v1) *(float2*)(out + (size_t)r1 * Dd + col) =
                        make_float2(c2 + b0, c3 + b1);
                }
            }
        }
    }
}

// ---------------- per-segment scatter (r-major, fp16 reads) -----------------
// blockIdx.y = relation; one 16-lane group per (r,dst) segment.
__global__ void seg_scatter(float* __restrict__ out, int n) {
    int gid  = blockIdx.x * blockDim.x + threadIdx.x;
    int dst  = gid >> 4, glan = gid & 15;
    if (dst >= n) return;
    int r = blockIdx.y;
    int seg = r * n + dst;
    int s = g_base[seg], e = g_base[seg + 1];
    if (e == s) return;
    const uint2* plane = (const uint2*)g_hw16 + (size_t)r * n * 16;
    float4 acc = make_float4(0.f, 0.f, 0.f, 0.f);
    for (int i = s; i < e; ++i) {
        uint2 u = plane[(size_t)g_ssrc[i] * 16 + glan];
        __half2 h0 = *reinterpret_cast<__half2*>(&u.x);
        __half2 h1 = *reinterpret_cast<__half2*>(&u.y);
        float2 f0 = __half22float2(h0), f1 = __half22float2(h1);
        acc.x += f0.x; acc.y += f0.y; acc.z += f1.x; acc.w += f1.y;
    }
    float sc = 1.0f / (float)(e - s);
    acc.x *= sc; acc.y *= sc; acc.z *= sc; acc.w *= sc;
    float* dp = out + (size_t)dst * Dd + glan * 4;
    asm volatile("red.global.add.v4.f32 [%0], {%1,%2,%3,%4};"
                 :: "l"(dp), "f"(acc.x), "f"(acc.y), "f"(acc.z), "f"(acc.w)
                 : "memory");
}

// ---------------------------------------------------------------------------
extern "C" void kernel_launch(void* const* d_in, const int* in_sizes, int n_in,
                              void* d_out, int out_size) {
    const int*   x    = (const int*)d_in[0];
    const int*   ei   = (const int*)d_in[1];
    const int*   et   = (const int*)d_in[2];
    const float* emb  = (const float*)d_in[3];
    const float* W1   = (const float*)d_in[4];
    const float* rt1  = (const float*)d_in[5];
    const float* b1   = (const float*)d_in[6];
    const float* W2   = (const float*)d_in[7];
    const float* rt2  = (const float*)d_in[8];
    const float* b2   = (const float*)d_in[9];
    float*       out  = (float*)d_out;

    int n  = in_sizes[0];
    int E_ = in_sizes[2];
    int S  = n * Rr;

    void *ph1, *pb;
    cudaGetSymbolAddress(&ph1, g_h1);
    cudaGetSymbolAddress(&pb,  g_base);
    float* h1   = (float*)ph1;
    int*   base = (int*)pb;

    cudaFuncSetAttribute(gemm_mma, cudaFuncAttributeMaxDynamicSharedMemorySize,
                         SM_TOTAL);

    // ---- one-time edge segment sort: seg = r*N + dst ----
    int nscan = (S + 1023) / 1024;
    zeroi_kernel<<<1024, 256>>>(base, S + 1);
    hist_kernel<<<4096, 256>>>(ei, et, n, E_);
    scan1_kernel<<<nscan, 256>>>(S);
    scan2_kernel<<<1, 256>>>(nscan);
    scan3_kernel<<<(S + 255) / 256, 256>>>(S, E_);
    place_kernel<<<4096, 256>>>(ei, et, n, E_);

    dim3 sgrid((n * 16 + 255) / 256, Rr);

    // ---- layer 1 ----
    splitb_kernel<<<(NCHUNK * 64 * 32 + 255) / 256, 256>>>(W1, rt1);
    gemm_mma<<<148, 512, SM_TOTAL>>>(emb, x, 0, b1, h1, n);
    seg_scatter<<<sgrid, 256>>>(h1, n);

    // ---- layer 2 ----
    splitb_kernel<<<(NCHUNK * 64 * 32 + 255) / 256, 256>>>(W2, rt2);
    gemm_mma<<<148, 512, SM_TOTAL>>>(h1, nullptr, 1, b2, out, n);
    seg_scatter<<<sgrid, 256>>>(out, n);
}

// round 16
// speedup vs baseline: 1.4351x; 1.4351x over previous
#include <cuda_runtime.h>
#include <cuda_bf16.h>
#include <cuda_fp16.h>
#include <cstdint>

#define Dd 64
#define Rr 8
#define MAXN 100000
#define MAXE 3200000
#define NCHUNK 9                  // 8 relations + root

// ---------------- device scratch (no allocation allowed) -------------------
__device__ __align__(256) unsigned g_hw16[(size_t)Rr * MAXN * 32]; // 102MB half2
__device__ __align__(256) float    g_h1[MAXN * Dd];
__device__ __align__(256) unsigned g_ahi[MAXN * 32];   // bf16x2 A hi
__device__ __align__(256) unsigned g_alo[MAXN * 32];   // bf16x2 A lo
__device__ __align__(256) unsigned g_bhi[NCHUNK * 64 * 32];
__device__ __align__(256) unsigned g_blo[NCHUNK * 64 * 32];
__device__ __align__(256) int      g_base[MAXN * Rr + 1]; // seg = r*N+dst
__device__ __align__(256) int      g_cur[MAXN * Rr];
__device__ __align__(256) int      g_bsum[1024];
__device__ __align__(256) int      g_ssrc[MAXE];          // seg-sorted src ids

// ---------------- sort kernels (seg = r*N + dst) ----------------------------
__global__ void zeroi_kernel(int* __restrict__ p, int n) {
    int i = blockIdx.x * blockDim.x + threadIdx.x;
    int stride = gridDim.x * blockDim.x;
    for (; i < n; i += stride) p[i] = 0;
}
__global__ void hist_kernel(const int* __restrict__ ei,
                            const int* __restrict__ et, int n, int E_) {
    int stride = gridDim.x * blockDim.x;
    for (int e = blockIdx.x * blockDim.x + threadIdx.x; e < E_; e += stride)
        atomicAdd(&g_base[et[e] * n + ei[E_ + e]], 1);
}
__global__ void scan1_kernel(int S) {
    __shared__ int sh[256];
    int tid = threadIdx.x;
    int i0 = blockIdx.x * 1024 + tid * 4;
    int v[4], t = 0;
    #pragma unroll
    for (int j = 0; j < 4; ++j) {
        int idx = i0 + j;
        v[j] = (idx < S) ? g_base[idx] : 0;
        t += v[j];
    }
    sh[tid] = t;
    __syncthreads();
    for (int off = 1; off < 256; off <<= 1) {
        int x = (tid >= off) ? sh[tid - off] : 0;
        __syncthreads();
        sh[tid] += x;
        __syncthreads();
    }
    int run = sh[tid] - t;
    if (tid == 255) g_bsum[blockIdx.x] = sh[255];
    #pragma unroll
    for (int j = 0; j < 4; ++j) {
        int idx = i0 + j;
        if (idx < S) g_base[idx] = run;
        run += v[j];
    }
}
__global__ void scan2_kernel(int nb) {
    __shared__ int sh[256];
    int tid = threadIdx.x;
    int v[4], t = 0;
    #pragma unroll
    for (int j = 0; j < 4; ++j) {
        int idx = tid * 4 + j;
        v[j] = (idx < nb) ? g_bsum[idx] : 0;
        t += v[j];
    }
    sh[tid] = t;
    __syncthreads();
    for (int off = 1; off < 256; off <<= 1) {
        int x = (tid >= off) ? sh[tid - off] : 0;
        __syncthreads();
        sh[tid] += x;
        __syncthreads();
    }
    int run = sh[tid] - t;
    #pragma unroll
    for (int j = 0; j < 4; ++j) {
        int idx = tid * 4 + j;
        if (idx < nb) g_bsum[idx] = run;
        run += v[j];
    }
}
__global__ void scan3_kernel(int S, int E_) {
    int i = blockIdx.x * blockDim.x + threadIdx.x;
    if (i < S) {
        int b = g_base[i] + g_bsum[i >> 10];
        g_base[i] = b;
        g_cur[i]  = b;
    }
    if (i == 0) g_base[S] = E_;
}
__global__ void place_kernel(const int* __restrict__ ei,
                             const int* __restrict__ et, int n, int E_) {
    int stride = gridDim.x * blockDim.x;
    for (int e = blockIdx.x * blockDim.x + threadIdx.x; e < E_; e += stride) {
        int seg = et[e] * n + ei[E_ + e];
        int pos = atomicAdd(&g_cur[seg], 1);
        g_ssrc[pos] = ei[e];
    }
}

// ---------------- bf16 split helpers ---------------------------------------
__device__ __forceinline__ void split2(float a, float b, unsigned& hi, unsigned& lo) {
    __nv_bfloat16 ha = __float2bfloat16_rn(a), hb = __float2bfloat16_rn(b);
    float ra = a - __bfloat162float(ha), rb = b - __bfloat162float(hb);
    __nv_bfloat162 H = __nv_bfloat162(ha, hb);
    __nv_bfloat162 L = __nv_bfloat162(__float2bfloat16_rn(ra), __float2bfloat16_rn(rb));
    hi = *reinterpret_cast<unsigned*>(&H);
    lo = *reinterpret_cast<unsigned*>(&L);
}

// mode 0: row = emb[x[node]]; mode 1: row = relu(h[node]).
__global__ void splita_kernel(const float* __restrict__ src,
                              const int* __restrict__ x, int n, int mode) {
    int total = n * 32;
    int stride = gridDim.x * blockDim.x;
    for (int j = blockIdx.x * blockDim.x + threadIdx.x; j < total; j += stride) {
        int node = j >> 5, q = j & 31;
        size_t row = (mode == 0) ? (size_t)x[node] : (size_t)node;
        float2 v = ((const float2*)src)[row * 32 + q];
        if (mode == 1) { v.x = fmaxf(v.x, 0.f); v.y = fmaxf(v.y, 0.f); }
        unsigned hi, lo;
        split2(v.x, v.y, hi, lo);
        g_ahi[j] = hi; g_alo[j] = lo;
    }
}

// B-split + transpose: [c][outcol][k] rows for ldmatrix row.col.
__global__ void splitb_kernel(const float* __restrict__ W,
                              const float* __restrict__ root) {
    int j = blockIdx.x * blockDim.x + threadIdx.x;
    if (j >= NCHUNK * 64 * 32) return;
    int q = j & 31, col = (j >> 5) & 63, c = j >> 11;
    const float* B = (c < 8) ? (W + c * 4096) : root;
    float a = B[(2 * q) * 64 + col];
    float b = B[(2 * q + 1) * 64 + col];
    unsigned hi, lo;
    split2(a, b, hi, lo);
    g_bhi[j] = hi; g_blo[j] = lo;
}

// ---------------- mma.sync GEMM -----------------------------------------
// chunks 0..7 -> fp16 hw planes; chunk 8 (root) -> fp32 out = C + bias.
#define BPITCH   144
#define SB_CHUNK (64 * BPITCH)
#define SB_HALF  (NCHUNK * SB_CHUNK)
#define SB_TOTAL (2 * SB_HALF)          // 165888 B
#define SM_BIAS  SB_TOTAL
#define SM_TOTAL (SM_BIAS + 256)

#define MMA(c0,c1,c2,c3, a, b0, b1)                                            \
    asm volatile("mma.sync.aligned.m16n8k16.row.col.f32.bf16.bf16.f32 "        \
                 "{%0,%1,%2,%3}, {%4,%5,%6,%7}, {%8,%9}, {%0,%1,%2,%3};"       \
                 : "+f"(c0), "+f"(c1), "+f"(c2), "+f"(c3)                      \
                 : "r"((a)[0]), "r"((a)[1]), "r"((a)[2]), "r"((a)[3]),         \
                   "r"(b0), "r"(b1))
#define LDSM_X2(b0, b1, addr)                                                  \
    asm volatile("ldmatrix.sync.aligned.m8n8.x2.shared.b16 {%0,%1}, [%2];"     \
                 : "=r"(b0), "=r"(b1) : "r"(addr))

__device__ __forceinline__ unsigned packh2(float a, float b) {
    __half2 h = __floats2half2_rn(a, b);
    return *reinterpret_cast<unsigned*>(&h);
}

__global__ __launch_bounds__(512, 1)
void gemm_mma(const float* __restrict__ bias, float* __restrict__ out,
              int nNodes) {
    extern __shared__ char sm[];
    int tid = threadIdx.x;

    for (int i = tid; i < NCHUNK * 64 * 32; i += 512) {
        int c = i >> 11, col = (i >> 5) & 63, q = i & 31;
        int off = c * SB_CHUNK + col * BPITCH + q * 4;
        *(unsigned*)(sm + off)           = g_bhi[i];
        *(unsigned*)(sm + SB_HALF + off) = g_blo[i];
    }
    if (tid < 64) ((float*)(sm + SM_BIAS))[tid] = bias[tid];
    __syncthreads();

    uint32_t smb;
    asm("{ .reg .u64 t; cvta.to.shared.u64 t, %1; cvt.u32.u64 %0, t; }"
        : "=r"(smb) : "l"(sm));
    const float* sbias = (const float*)(sm + SM_BIAS);

    int warp = tid >> 5, lane = tid & 31;
    int qt = lane & 3;
    uint32_t bbase = smb + (lane & 7) * BPITCH + ((lane >> 3) & 1) * 16;

    int ntiles = (nNodes + 255) >> 8;
    for (int tile = blockIdx.x; tile < ntiles; tile += gridDim.x) {
        int nbase = tile * 256 + warp * 16;
        int r0 = nbase + (lane >> 2);
        int r1 = r0 + 8;
        bool v0 = r0 < nNodes, v1 = r1 < nNodes;

        unsigned ah[4][4], al[4][4];
        #pragma unroll
        for (int s = 0; s < 4; ++s) {
            int i0 = s * 8 + qt;
            ah[s][0] = v0 ? g_ahi[(size_t)r0 * 32 + i0]     : 0u;
            ah[s][1] = v1 ? g_ahi[(size_t)r1 * 32 + i0]     : 0u;
            ah[s][2] = v0 ? g_ahi[(size_t)r0 * 32 + i0 + 4] : 0u;
            ah[s][3] = v1 ? g_ahi[(size_t)r1 * 32 + i0 + 4] : 0u;
            al[s][0] = v0 ? g_alo[(size_t)r0 * 32 + i0]     : 0u;
            al[s][1] = v1 ? g_alo[(size_t)r1 * 32 + i0]     : 0u;
            al[s][2] = v0 ? g_alo[(size_t)r0 * 32 + i0 + 4] : 0u;
            al[s][3] = v1 ? g_alo[(size_t)r1 * 32 + i0 + 4] : 0u;
        }

        for (int c = 0; c < NCHUNK; ++c) {
            uint32_t cb = bbase + c * SB_CHUNK;
            unsigned* dst0 = g_hw16 + ((size_t)c * nNodes + r0) * 32;
            unsigned* dst1 = g_hw16 + ((size_t)c * nNodes + r1) * 32;
            #pragma unroll
            for (int j = 0; j < 8; ++j) {
                float c0 = 0.f, c1 = 0.f, c2 = 0.f, c3 = 0.f;
                uint32_t jb = cb + j * 8 * BPITCH;
                #pragma unroll
                for (int s = 0; s < 4; ++s) {
                    unsigned bh0, bh1, bl0, bl1;
                    LDSM_X2(bh0, bh1, jb + s * 32);
                    LDSM_X2(bl0, bl1, jb + s * 32 + SB_HALF);
                    MMA(c0, c1, c2, c3, ah[s], bh0, bh1);
                    MMA(c0, c1, c2, c3, ah[s], bl0, bl1);
                    MMA(c0, c1, c2, c3, al[s], bh0, bh1);
                }
                if (c < 8) {
                    int hcol = j * 4 + qt;     // half2 index within row
                    if (v0) dst0[hcol] = packh2(c0, c1);
                    if (v1) dst1[hcol] = packh2(c2, c3);
                } else {
                    int col = j * 8 + qt * 2;
                    float b0 = sbias[col], b1 = sbias[col + 1];
                    if (v0) *(float2*)(out + (size_t)r0 * Dd + col) =
                        make_float2(c0 + b0, c1 + b1);
                    if (v1) *(float2*)(out + (size_t)r1 * Dd + col) =
                        make_float2(c2 + b0, c3 + b1);
                }
            }
        }
    }
}

// ---------------- per-segment scatter (r-major, fp16 reads) -----------------
// blockIdx.y = relation; one 8-lane group per (r,dst) segment, uint4 loads.
__global__ void seg_scatter(float* __restrict__ out, int n) {
    int gid  = blockIdx.x * blockDim.x + threadIdx.x;
    int dst  = gid >> 3, glan = gid & 7;
    if (dst >= n) return;
    int r = blockIdx.y;
    int seg = r * n + dst;
    int s = g_base[seg], e = g_base[seg + 1];
    if (e == s) return;
    const uint4* plane = (const uint4*)g_hw16 + (size_t)r * n * 8;
    float4 acc0 = make_float4(0.f, 0.f, 0.f, 0.f);
    float4 acc1 = make_float4(0.f, 0.f, 0.f, 0.f);
    for (int i = s; i < e; ++i) {
        uint4 u = plane[(size_t)g_ssrc[i] * 8 + glan];
        __half2 h0 = *reinterpret_cast<__half2*>(&u.x);
        __half2 h1 = *reinterpret_cast<__half2*>(&u.y);
        __half2 h2 = *reinterpret_cast<__half2*>(&u.z);
        __half2 h3 = *reinterpret_cast<__half2*>(&u.w);
        float2 f0 = __half22float2(h0), f1 = __half22float2(h1);
        float2 f2 = __half22float2(h2), f3 = __half22float2(h3);
        acc0.x += f0.x; acc0.y += f0.y; acc0.z += f1.x; acc0.w += f1.y;
        acc1.x += f2.x; acc1.y += f2.y; acc1.z += f3.x; acc1.w += f3.y;
    }
    float sc = 1.0f / (float)(e - s);
    acc0.x *= sc; acc0.y *= sc; acc0.z *= sc; acc0.w *= sc;
    acc1.x *= sc; acc1.y *= sc; acc1.z *= sc; acc1.w *= sc;
    float* dp = out + (size_t)dst * Dd + glan * 8;
    asm volatile("red.global.add.v4.f32 [%0], {%1,%2,%3,%4};"
                 :: "l"(dp), "f"(acc0.x), "f"(acc0.y), "f"(acc0.z), "f"(acc0.w)
                 : "memory");
    asm volatile("red.global.add.v4.f32 [%0], {%1,%2,%3,%4};"
                 :: "l"(dp + 4), "f"(acc1.x), "f"(acc1.y), "f"(acc1.z), "f"(acc1.w)
                 : "memory");
}

// ---------------------------------------------------------------------------
extern "C" void kernel_launch(void* const* d_in, const int* in_sizes, int n_in,
                              void* d_out, int out_size) {
    const int*   x    = (const int*)d_in[0];
    const int*   ei   = (const int*)d_in[1];
    const int*   et   = (const int*)d_in[2];
    const float* emb  = (const float*)d_in[3];
    const float* W1   = (const float*)d_in[4];
    const float* rt1  = (const float*)d_in[5];
    const float* b1   = (const float*)d_in[6];
    const float* W2   = (const float*)d_in[7];
    const float* rt2  = (const float*)d_in[8];
    const float* b2   = (const float*)d_in[9];
    float*       out  = (float*)d_out;

    int n  = in_sizes[0];
    int E_ = in_sizes[2];
    int S  = n * Rr;

    void *ph1, *pb;
    cudaGetSymbolAddress(&ph1, g_h1);
    cudaGetSymbolAddress(&pb,  g_base);
    float* h1   = (float*)ph1;
    int*   base = (int*)pb;

    cudaFuncSetAttribute(gemm_mma, cudaFuncAttributeMaxDynamicSharedMemorySize,
                         SM_TOTAL);

    // ---- one-time edge segment sort: seg = r*N + dst ----
    int nscan = (S + 1023) / 1024;
    zeroi_kernel<<<1024, 256>>>(base, S + 1);
    hist_kernel<<<4096, 256>>>(ei, et, n, E_);
    scan1_kernel<<<nscan, 256>>>(S);
    scan2_kernel<<<1, 256>>>(nscan);
    scan3_kernel<<<(S + 255) / 256, 256>>>(S, E_);
    place_kernel<<<4096, 256>>>(ei, et, n, E_);

    dim3 sgrid((n * 8 + 255) / 256, Rr);

    // ---- layer 1 ----
    splitb_kernel<<<(NCHUNK * 64 * 32 + 255) / 256, 256>>>(W1, rt1);
    splita_kernel<<<2048, 256>>>(emb, x, n, 0);
    gemm_mma<<<148, 512, SM_TOTAL>>>(b1, h1, n);
    seg_scatter<<<sgrid, 256>>>(h1, n);

    // ---- layer 2 ----
    splitb_kernel<<<(NCHUNK * 64 * 32 + 255) / 256, 256>>>(W2, rt2);
    splita_kernel<<<2048, 256>>>(h1, nullptr, n, 1);
    gemm_mma<<<148, 512, SM_TOTAL>>>(b2, out, n);
    seg_scatter<<<sgrid, 256>>>(out, n);
}

// round 17
// speedup vs baseline: 1.4888x; 1.0374x over previous
#include <cuda_runtime.h>
#include <cuda_bf16.h>
#include <cuda_fp16.h>
#include <cstdint>

#define Dd 64
#define Rr 8
#define MAXN 100000
#define MAXE 3200000
#define NCHUNK 9                  // 8 relations + root

// ---------------- device scratch (no allocation allowed) -------------------
__device__ __align__(256) unsigned g_hw16[(size_t)Rr * MAXN * 32]; // 102MB half2
__device__ __align__(256) float    g_h1[MAXN * Dd];
__device__ __align__(256) unsigned g_ahi[MAXN * 32];   // bf16x2 A hi
__device__ __align__(256) unsigned g_alo[MAXN * 32];   // bf16x2 A lo
__device__ __align__(256) unsigned g_bhi[NCHUNK * 64 * 32];
__device__ __align__(256) unsigned g_blo[NCHUNK * 64 * 32];
__device__ __align__(256) int      g_base[MAXN * Rr + 1]; // seg = r*N+dst
__device__ __align__(256) int      g_cur[MAXN * Rr];
__device__ __align__(256) int      g_bsum[1024];
__device__ __align__(256) int      g_ssrc[MAXE];          // seg-sorted src ids

// ---------------- sort kernels (seg = r*N + dst) ----------------------------
__global__ void zeroi_kernel(int* __restrict__ p, int n) {
    int i = blockIdx.x * blockDim.x + threadIdx.x;
    int stride = gridDim.x * blockDim.x;
    for (; i < n; i += stride) p[i] = 0;
}
__global__ void hist_kernel(const int* __restrict__ ei,
                            const int* __restrict__ et, int n, int E_) {
    int stride = gridDim.x * blockDim.x;
    for (int e = blockIdx.x * blockDim.x + threadIdx.x; e < E_; e += stride)
        atomicAdd(&g_base[et[e] * n + ei[E_ + e]], 1);
}
__global__ void scan1_kernel(int S) {
    __shared__ int sh[256];
    int tid = threadIdx.x;
    int i0 = blockIdx.x * 1024 + tid * 4;
    int v[4], t = 0;
    #pragma unroll
    for (int j = 0; j < 4; ++j) {
        int idx = i0 + j;
        v[j] = (idx < S) ? g_base[idx] : 0;
        t += v[j];
    }
    sh[tid] = t;
    __syncthreads();
    for (int off = 1; off < 256; off <<= 1) {
        int x = (tid >= off) ? sh[tid - off] : 0;
        __syncthreads();
        sh[tid] += x;
        __syncthreads();
    }
    int run = sh[tid] - t;
    if (tid == 255) g_bsum[blockIdx.x] = sh[255];
    #pragma unroll
    for (int j = 0; j < 4; ++j) {
        int idx = i0 + j;
        if (idx < S) g_base[idx] = run;
        run += v[j];
    }
}
__global__ void scan2_kernel(int nb) {
    __shared__ int sh[256];
    int tid = threadIdx.x;
    int v[4], t = 0;
    #pragma unroll
    for (int j = 0; j < 4; ++j) {
        int idx = tid * 4 + j;
        v[j] = (idx < nb) ? g_bsum[idx] : 0;
        t += v[j];
    }
    sh[tid] = t;
    __syncthreads();
    for (int off = 1; off < 256; off <<= 1) {
        int x = (tid >= off) ? sh[tid - off] : 0;
        __syncthreads();
        sh[tid] += x;
        __syncthreads();
    }
    int run = sh[tid] - t;
    #pragma unroll
    for (int j = 0; j < 4; ++j) {
        int idx = tid * 4 + j;
        if (idx < nb) g_bsum[idx] = run;
        run += v[j];
    }
}
__global__ void scan3_kernel(int S, int E_) {
    int i = blockIdx.x * blockDim.x + threadIdx.x;
    if (i < S) {
        int b = g_base[i] + g_bsum[i >> 10];
        g_base[i] = b;
        g_cur[i]  = b;
    }
    if (i == 0) g_base[S] = E_;
}
__global__ void place_kernel(const int* __restrict__ ei,
                             const int* __restrict__ et, int n, int E_) {
    int stride = gridDim.x * blockDim.x;
    for (int e = blockIdx.x * blockDim.x + threadIdx.x; e < E_; e += stride) {
        int seg = et[e] * n + ei[E_ + e];
        int pos = atomicAdd(&g_cur[seg], 1);
        g_ssrc[pos] = ei[e];
    }
}

// ---------------- bf16 split helpers ---------------------------------------
__device__ __forceinline__ void split2(float a, float b, unsigned& hi, unsigned& lo) {
    __nv_bfloat16 ha = __float2bfloat16_rn(a), hb = __float2bfloat16_rn(b);
    float ra = a - __bfloat162float(ha), rb = b - __bfloat162float(hb);
    __nv_bfloat162 H = __nv_bfloat162(ha, hb);
    __nv_bfloat162 L = __nv_bfloat162(__float2bfloat16_rn(ra), __float2bfloat16_rn(rb));
    hi = *reinterpret_cast<unsigned*>(&H);
    lo = *reinterpret_cast<unsigned*>(&L);
}

// mode 0: row = emb[x[node]]; mode 1: row = relu(h[node]).
__global__ void splita_kernel(const float* __restrict__ src,
                              const int* __restrict__ x, int n, int mode) {
    int total = n * 32;
    int stride = gridDim.x * blockDim.x;
    for (int j = blockIdx.x * blockDim.x + threadIdx.x; j < total; j += stride) {
        int node = j >> 5, q = j & 31;
        size_t row = (mode == 0) ? (size_t)x[node] : (size_t)node;
        float2 v = ((const float2*)src)[row * 32 + q];
        if (mode == 1) { v.x = fmaxf(v.x, 0.f); v.y = fmaxf(v.y, 0.f); }
        unsigned hi, lo;
        split2(v.x, v.y, hi, lo);
        g_ahi[j] = hi; g_alo[j] = lo;
    }
}

// B-split + transpose: [c][outcol][k] rows for ldmatrix row.col.
__global__ void splitb_kernel(const float* __restrict__ W,
                              const float* __restrict__ root) {
    int j = blockIdx.x * blockDim.x + threadIdx.x;
    if (j >= NCHUNK * 64 * 32) return;
    int q = j & 31, col = (j >> 5) & 63, c = j >> 11;
    const float* B = (c < 8) ? (W + c * 4096) : root;
    float a = B[(2 * q) * 64 + col];
    float b = B[(2 * q + 1) * 64 + col];
    unsigned hi, lo;
    split2(a, b, hi, lo);
    g_bhi[j] = hi; g_blo[j] = lo;
}

// ---------------- mma.sync GEMM -----------------------------------------
// chunks 0..7 -> fp16 hw planes; chunk 8 (root) -> fp32 out = C + bias.
#define BPITCH   144
#define SB_CHUNK (64 * BPITCH)
#define SB_HALF  (NCHUNK * SB_CHUNK)
#define SB_TOTAL (2 * SB_HALF)          // 165888 B
#define SM_BIAS  SB_TOTAL
#define SM_TOTAL (SM_BIAS + 256)

#define MMA(c0,c1,c2,c3, a, b0, b1)                                            \
    asm volatile("mma.sync.aligned.m16n8k16.row.col.f32.bf16.bf16.f32 "        \
                 "{%0,%1,%2,%3}, {%4,%5,%6,%7}, {%8,%9}, {%0,%1,%2,%3};"       \
                 : "+f"(c0), "+f"(c1), "+f"(c2), "+f"(c3)                      \
                 : "r"((a)[0]), "r"((a)[1]), "r"((a)[2]), "r"((a)[3]),         \
                   "r"(b0), "r"(b1))
#define LDSM_X2(b0, b1, addr)                                                  \
    asm volatile("ldmatrix.sync.aligned.m8n8.x2.shared.b16 {%0,%1}, [%2];"     \
                 : "=r"(b0), "=r"(b1) : "r"(addr))

__device__ __forceinline__ unsigned packh2(float a, float b) {
    __half2 h = __floats2half2_rn(a, b);
    return *reinterpret_cast<unsigned*>(&h);
}

__global__ __launch_bounds__(512, 1)
void gemm_mma(const float* __restrict__ bias, float* __restrict__ out,
              int nNodes) {
    extern __shared__ char sm[];
    int tid = threadIdx.x;

    for (int i = tid; i < NCHUNK * 64 * 32; i += 512) {
        int c = i >> 11, col = (i >> 5) & 63, q = i & 31;
        int off = c * SB_CHUNK + col * BPITCH + q * 4;
        *(unsigned*)(sm + off)           = g_bhi[i];
        *(unsigned*)(sm + SB_HALF + off) = g_blo[i];
    }
    if (tid < 64) ((float*)(sm + SM_BIAS))[tid] = bias[tid];
    __syncthreads();

    uint32_t smb;
    asm("{ .reg .u64 t; cvta.to.shared.u64 t, %1; cvt.u32.u64 %0, t; }"
        : "=r"(smb) : "l"(sm));
    const float* sbias = (const float*)(sm + SM_BIAS);

    int warp = tid >> 5, lane = tid & 31;
    int qt = lane & 3;
    uint32_t bbase = smb + (lane & 7) * BPITCH + ((lane >> 3) & 1) * 16;

    int ntiles = (nNodes + 255) >> 8;
    for (int tile = blockIdx.x; tile < ntiles; tile += gridDim.x) {
        int nbase = tile * 256 + warp * 16;
        int r0 = nbase + (lane >> 2);
        int r1 = r0 + 8;
        bool v0 = r0 < nNodes, v1 = r1 < nNodes;

        unsigned ah[4][4], al[4][4];
        #pragma unroll
        for (int s = 0; s < 4; ++s) {
            int i0 = s * 8 + qt;
            ah[s][0] = v0 ? g_ahi[(size_t)r0 * 32 + i0]     : 0u;
            ah[s][1] = v1 ? g_ahi[(size_t)r1 * 32 + i0]     : 0u;
            ah[s][2] = v0 ? g_ahi[(size_t)r0 * 32 + i0 + 4] : 0u;
            ah[s][3] = v1 ? g_ahi[(size_t)r1 * 32 + i0 + 4] : 0u;
            al[s][0] = v0 ? g_alo[(size_t)r0 * 32 + i0]     : 0u;
            al[s][1] = v1 ? g_alo[(size_t)r1 * 32 + i0]     : 0u;
            al[s][2] = v0 ? g_alo[(size_t)r0 * 32 + i0 + 4] : 0u;
            al[s][3] = v1 ? g_alo[(size_t)r1 * 32 + i0 + 4] : 0u;
        }

        for (int c = 0; c < NCHUNK; ++c) {
            uint32_t cb = bbase + c * SB_CHUNK;
            unsigned* dst0 = g_hw16 + ((size_t)c * nNodes + r0) * 32;
            unsigned* dst1 = g_hw16 + ((size_t)c * nNodes + r1) * 32;
            #pragma unroll
            for (int j = 0; j < 8; ++j) {
                float c0 = 0.f, c1 = 0.f, c2 = 0.f, c3 = 0.f;
                uint32_t jb = cb + j * 8 * BPITCH;
                #pragma unroll
                for (int s = 0; s < 4; ++s) {
                    unsigned bh0, bh1, bl0, bl1;
                    LDSM_X2(bh0, bh1, jb + s * 32);
                    LDSM_X2(bl0, bl1, jb + s * 32 + SB_HALF);
                    MMA(c0, c1, c2, c3, ah[s], bh0, bh1);
                    MMA(c0, c1, c2, c3, ah[s], bl0, bl1);
                    MMA(c0, c1, c2, c3, al[s], bh0, bh1);
                }
                if (c < 8) {
                    int hcol = j * 4 + qt;     // half2 index within row
                    if (v0) dst0[hcol] = packh2(c0, c1);
                    if (v1) dst1[hcol] = packh2(c2, c3);
                } else {
                    int col = j * 8 + qt * 2;
                    float b0 = sbias[col], b1 = sbias[col + 1];
                    if (v0) *(float2*)(out + (size_t)r0 * Dd + col) =
                        make_float2(c0 + b0, c1 + b1);
                    if (v1) *(float2*)(out + (size_t)r1 * Dd + col) =
                        make_float2(c2 + b0, c3 + b1);
                }
            }
        }
    }
}

// ---------------- per-segment scatter (r-major, fp16 reads) -----------------
// blockIdx.y = relation; one 8-lane group per (r,dst) segment, uint4 loads.
__global__ void seg_scatter(float* __restrict__ out, int n) {
    int gid  = blockIdx.x * blockDim.x + threadIdx.x;
    int dst  = gid >> 3, glan = gid & 7;
    if (dst >= n) return;
    int r = blockIdx.y;
    int seg = r * n + dst;
    int s = g_base[seg], e = g_base[seg + 1];
    if (e == s) return;
    const uint4* plane = (const uint4*)g_hw16 + (size_t)r * n * 8;
    float4 acc0 = make_float4(0.f, 0.f, 0.f, 0.f);
    float4 acc1 = make_float4(0.f, 0.f, 0.f, 0.f);
    for (int i = s; i < e; ++i) {
        uint4 u = plane[(size_t)g_ssrc[i] * 8 + glan];
        __half2 h0 = *reinterpret_cast<__half2*>(&u.x);
        __half2 h1 = *reinterpret_cast<__half2*>(&u.y);
        __half2 h2 = *reinterpret_cast<__half2*>(&u.z);
        __half2 h3 = *reinterpret_cast<__half2*>(&u.w);
        float2 f0 = __half22float2(h0), f1 = __half22float2(h1);
        float2 f2 = __half22float2(h2), f3 = __half22float2(h3);
        acc0.x += f0.x; acc0.y += f0.y; acc0.z += f1.x; acc0.w += f1.y;
        acc1.x += f2.x; acc1.y += f2.y; acc1.z += f3.x; acc1.w += f3.y;
    }
    float sc = 1.0f / (float)(e - s);
    acc0.x *= sc; acc0.y *= sc; acc0.z *= sc; acc0.w *= sc;
    acc1.x *= sc; acc1.y *= sc; acc1.z *= sc; acc1.w *= sc;
    float* dp = out + (size_t)dst * Dd + glan * 8;
    asm volatile("red.global.add.v4.f32 [%0], {%1,%2,%3,%4};"
                 :: "l"(dp), "f"(acc0.x), "f"(acc0.y), "f"(acc0.z), "f"(acc0.w)
                 : "memory");
    asm volatile("red.global.add.v4.f32 [%0], {%1,%2,%3,%4};"
                 :: "l"(dp + 4), "f"(acc1.x), "f"(acc1.y), "f"(acc1.z), "f"(acc1.w)
                 : "memory");
}

// ---------------------------------------------------------------------------
extern "C" void kernel_launch(void* const* d_in, const int* in_sizes, int n_in,
                              void* d_out, int out_size) {
    const int*   x    = (const int*)d_in[0];
    const int*   ei   = (const int*)d_in[1];
    const int*   et   = (const int*)d_in[2];
    const float* emb  = (const float*)d_in[3];
    const float* W1   = (const float*)d_in[4];
    const float* rt1  = (const float*)d_in[5];
    const float* b1   = (const float*)d_in[6];
    const float* W2   = (const float*)d_in[7];
    const float* rt2  = (const float*)d_in[8];
    const float* b2   = (const float*)d_in[9];
    float*       out  = (float*)d_out;

    int n  = in_sizes[0];
    int E_ = in_sizes[2];
    int S  = n * Rr;

    void *ph1, *pb;
    cudaGetSymbolAddress(&ph1, g_h1);
    cudaGetSymbolAddress(&pb,  g_base);
    float* h1   = (float*)ph1;
    int*   base = (int*)pb;

    cudaFuncSetAttribute(gemm_mma, cudaFuncAttributeMaxDynamicSharedMemorySize,
                         SM_TOTAL);

    // lazily-created side stream + fork/join events (host resources only;
    // created on the uncaptured correctness call, reused inside the graph)
    static cudaStream_t s2 = nullptr;
    static cudaEvent_t ev_fork = nullptr, ev_join = nullptr;
    if (!s2) {
        cudaStreamCreateWithFlags(&s2, cudaStreamNonBlocking);
        cudaEventCreateWithFlags(&ev_fork, cudaEventDisableTiming);
        cudaEventCreateWithFlags(&ev_join, cudaEventDisableTiming);
    }

    // ---- fork: edge segment sort (seg = r*N + dst) on side stream ----
    cudaEventRecord(ev_fork, 0);
    cudaStreamWaitEvent(s2, ev_fork, 0);
    int nscan = (S + 1023) / 1024;
    zeroi_kernel<<<1024, 256, 0, s2>>>(base, S + 1);
    hist_kernel<<<4096, 256, 0, s2>>>(ei, et, n, E_);
    scan1_kernel<<<nscan, 256, 0, s2>>>(S);
    scan2_kernel<<<1, 256, 0, s2>>>(nscan);
    scan3_kernel<<<(S + 255) / 256, 256, 0, s2>>>(S, E_);
    place_kernel<<<4096, 256, 0, s2>>>(ei, et, n, E_);
    cudaEventRecord(ev_join, s2);

    dim3 sgrid((n * 8 + 255) / 256, Rr);

    // ---- layer 1 (main stream; independent of the sort until scatter) ----
    splitb_kernel<<<(NCHUNK * 64 * 32 + 255) / 256, 256>>>(W1, rt1);
    splita_kernel<<<2048, 256>>>(emb, x, n, 0);
    gemm_mma<<<148, 512, SM_TOTAL>>>(b1, h1, n);
    cudaStreamWaitEvent(0, ev_join, 0);    // join: scatter needs sorted edges
    seg_scatter<<<sgrid, 256>>>(h1, n);

    // ---- layer 2 ----
    splitb_kernel<<<(NCHUNK * 64 * 32 + 255) / 256, 256>>>(W2, rt2);
    splita_kernel<<<2048, 256>>>(h1, nullptr, n, 1);
    gemm_mma<<<148, 512, SM_TOTAL>>>(b2, out, n);
    seg_scatter<<<sgrid, 256>>>(out, n);
}